// round 12
// baseline (speedup 1.0000x reference)
#include <cuda_runtime.h>
#include <cuda_bf16.h>
#include <math.h>
#include <stdint.h>

// Inter-layer scratch + sync (allocation-free rule: __device__ globals).
__device__ float g_out0[729];
__device__ float g_out1[27];
__device__ float g_uR1[27 * 32];     // layer1 backward half-results
__device__ unsigned g_grp[27];       // per-layer1-chain producer counters
__device__ unsigned g_half1[27];     // layer1 backward-half done flags
__device__ unsigned g_ctr1;          // layer1 completion counter

#define PI_HALF 1.57079632679489662f
#define STAGE_FLOATS 2048
#define FWD_STAGES 13                 // layer1 fwd: stages 0..12; bwd: 24..13
#define FULL 0xffffffffu

// ---------------- helpers ----------------
__device__ __forceinline__ float warp_sum(float v) {
#pragma unroll
    for (int o = 16; o > 0; o >>= 1)
        v += __shfl_down_sync(FULL, v, o);
    return v;
}
__device__ __forceinline__ void l2_prefetch_line(const float* p) {
    asm volatile("prefetch.global.L2 [%0];" :: "l"(p));
}
__device__ __forceinline__ void spin_until(const unsigned* c, unsigned target) {
    unsigned v;
    do {
        asm volatile("ld.global.acquire.gpu.u32 %0, [%1];"
                     : "=r"(v) : "l"(c) : "memory");
        if (v >= target) return;
        __nanosleep(128);
    } while (true);
}

// ---------- WIDE forward step: 16 x LDG.128 per stage ----------
// Stage = 25x[32 rows x 2 phys x 32 cols] floats. Chunk i (512 B) = rows 2i,2i+1.
// Lane L holds A[2i + (L>>4)][(L>>3)&1][4*(L&7) .. +3].
// v_new[e] = sum_d v[d] * (c*A[d][0][e] + s*A[d][1][e])
__device__ __forceinline__ float step_fwd_wide(const float* __restrict__ g,
                                               float v, int t, float c, float s) {
    const int dsel = t >> 4;
    const float4* __restrict__ base = (const float4*)g;
    float4 q[16];
#pragma unroll
    for (int i = 0; i < 16; i++)
        q[i] = __ldcs(&base[i * 32 + t]);          // 512 B / instr, coalesced

    float a0 = 0.f, a1 = 0.f, a2 = 0.f, a3 = 0.f;
#pragma unroll
    for (int i = 0; i < 16; i++) {
        const float vd = __shfl_sync(FULL, v, 2 * i + dsel);
        a0 = fmaf(vd, q[i].x, a0);
        a1 = fmaf(vd, q[i].y, a1);
        a2 = fmaf(vd, q[i].z, a2);
        a3 = fmaf(vd, q[i].w, a3);
    }
    // sum d-parity halves (lanes L and L^16 share (p, e-group))
    a0 += __shfl_xor_sync(FULL, a0, 16);
    a1 += __shfl_xor_sync(FULL, a1, 16);
    a2 += __shfl_xor_sync(FULL, a2, 16);
    a3 += __shfl_xor_sync(FULL, a3, 16);
    // combine p=0 / p=1 partners (lanes L and L^8)
    const float b0 = __shfl_xor_sync(FULL, a0, 8);
    const float b1 = __shfl_xor_sync(FULL, a1, 8);
    const float b2 = __shfl_xor_sync(FULL, a2, 8);
    const float b3 = __shfl_xor_sync(FULL, a3, 8);
    float o0, o1, o2, o3;
    if (((t >> 3) & 1) == 0) {
        o0 = fmaf(c, a0, s * b0); o1 = fmaf(c, a1, s * b1);
        o2 = fmaf(c, a2, s * b2); o3 = fmaf(c, a3, s * b3);
    } else {
        o0 = fmaf(c, b0, s * a0); o1 = fmaf(c, b1, s * a1);
        o2 = fmaf(c, b2, s * a2); o3 = fmaf(c, b3, s * a3);
    }
    // distribute: lane m wants e=m -> source lane m>>2 (e-group), component m&3
    const int src = t >> 2;
    const float w0 = __shfl_sync(FULL, o0, src);
    const float w1 = __shfl_sync(FULL, o1, src);
    const float w2 = __shfl_sync(FULL, o2, src);
    const float w3 = __shfl_sync(FULL, o3, src);
    const int j = t & 3;
    return (j == 0) ? w0 : (j == 1) ? w1 : (j == 2) ? w2 : w3;
}

__device__ __forceinline__ float chain_fwd_wide(const float* __restrict__ mid,
                                                int nst, float v,
                                                float cemb, float semb, int t) {
#pragma unroll 1
    for (int m = 0; m < nst; m++) {
        const float c = __shfl_sync(FULL, cemb, m + 1);
        const float s = __shfl_sync(FULL, semb, m + 1);
        v = step_fwd_wide(mid + m * STAGE_FLOATS, v, t, c, s);
    }
    return v;
}

// Backward step (tail only; data is L2-warm, few warps alive): per-lane row loads.
__device__ __forceinline__ float step_bwd(const float* __restrict__ g, float u,
                                          int t, float c, float s) {
    const float4* __restrict__ rp = (const float4*)(g + t * 64);
    float4 q[16];
#pragma unroll
    for (int i = 0; i < 16; i++) q[i] = rp[i];
    float acc0 = 0.f, acc1 = 0.f;
#pragma unroll
    for (int i = 0; i < 8; i++) {
        const float4 a = q[i];
        const float4 b = q[8 + i];
        float ue;
        ue = __shfl_sync(FULL, u, 4 * i + 0);
        acc0 = fmaf(a.x, ue, acc0);  acc1 = fmaf(b.x, ue, acc1);
        ue = __shfl_sync(FULL, u, 4 * i + 1);
        acc0 = fmaf(a.y, ue, acc0);  acc1 = fmaf(b.y, ue, acc1);
        ue = __shfl_sync(FULL, u, 4 * i + 2);
        acc0 = fmaf(a.z, ue, acc0);  acc1 = fmaf(b.z, ue, acc1);
        ue = __shfl_sync(FULL, u, 4 * i + 3);
        acc0 = fmaf(a.w, ue, acc0);  acc1 = fmaf(b.w, ue, acc1);
    }
    return fmaf(acc0, c, acc1 * s);
}

__global__ void reset_kernel() {
    const int i = threadIdx.x;
    if (i < 27) { g_grp[i] = 0; g_half1[i] = 0; }
    if (i == 27) g_ctr1 = 0;
}

// 729 blocks x 32 threads, one wave.
//  all blocks : layer0 chain n = blockIdx.x
//  n <  27    : layer1 forward half of chain n + combine (+ final for n==0)
//  27<=n<54   : layer1 backward half of chain n-27
__global__ void __launch_bounds__(32)
fused_kernel(const float* __restrict__ img,
             const float* __restrict__ l0f, const float* __restrict__ l0m,
             const float* __restrict__ l0l,
             const float* __restrict__ l1f, const float* __restrict__ l1m,
             const float* __restrict__ l1l,
             const float* __restrict__ ff,  const float* __restrict__ fm,
             const float* __restrict__ fl,
             float* __restrict__ out)
{
    const int n = blockIdx.x;
    const int t = threadIdx.x;

    // Embedding in registers: lane t (t<27) holds cos/sin for site t.
    float cemb = 0.0f, semb = 0.0f;
    if (t < 27) {
        const int bh = n / 81, bv = (n / 9) % 9, bd = n % 9;
        const int x = t / 9, y = (t / 3) % 3, z = t % 3;
        const float val = img[(3 * bh + x) * 729 + (3 * bv + y) * 27 + (3 * bd + z)];
        sincosf(PI_HALF * val, &semb, &cemb);
    }

    // ---------- Layer 0 ----------
    const float* gm0 = l0m + (long)n * (25 * STAGE_FLOATS);
    {
        const float c0 = __shfl_sync(FULL, cemb, 0);
        const float s0 = __shfl_sync(FULL, semb, 0);
        const float* f0 = l0f + n * 64;
        float v = fmaf(f0[t], c0, f0[32 + t] * s0);

        v = chain_fwd_wide(gm0, 25, v, cemb, semb, t);

        const float c26 = __shfl_sync(FULL, cemb, 26);
        const float s26 = __shfl_sync(FULL, semb, 26);
        const float* ln = l0l + n * 64;
        const float pv = v * fmaf(ln[2 * t], c26, ln[2 * t + 1] * s26);
        const float r = warp_sum(pv);
        if (t == 0) {
            g_out0[n] = r;
            __threadfence();
            const int X = n / 81, Y = (n / 9) % 9, Z = n % 9;
            atomicAdd(&g_grp[(X / 3) * 9 + (Y / 3) * 3 + (Z / 3)], 1u);
        }
    }
    if (n >= 54) return;

    if (n >= 27) {
        // ---------- Layer 1 backward half (blocks 27..53, chain cidx) ----------
        const int cidx = n - 27;
        const float* gm1 = l1m + cidx * (25 * STAGE_FLOATS);
        for (int i = t; i < (25 - FWD_STAGES) * 64; i += 32)   // L2-warm before spin
            l2_prefetch_line(gm1 + FWD_STAGES * STAGE_FLOATS + i * 32);
        spin_until(&g_grp[cidx], 27u);

        if (t < 27) {
            const int bh = cidx / 9, bv = (cidx / 3) % 3, bd = cidx % 3;
            const int x = t / 9, y = (t / 3) % 3, z = t % 3;
            const float val = __ldcg(&g_out0[(3 * bh + x) * 81 + (3 * bv + y) * 9 + (3 * bd + z)]);
            sincosf(PI_HALF * val, &semb, &cemb);
        }
        const float c26 = __shfl_sync(FULL, cemb, 26);
        const float s26 = __shfl_sync(FULL, semb, 26);
        const float* l1 = l1l + cidx * 64;
        float u = fmaf(l1[2 * t], c26, l1[2 * t + 1] * s26);
#pragma unroll 1
        for (int m = 24; m >= FWD_STAGES; m--) {
            const float c = __shfl_sync(FULL, cemb, m + 1);
            const float s = __shfl_sync(FULL, semb, m + 1);
            u = step_bwd(gm1 + m * STAGE_FLOATS, u, t, c, s);
        }
        g_uR1[cidx * 32 + t] = u;
        __threadfence();
        if (t == 0) atomicAdd(&g_half1[cidx], 1u);
        return;
    }

    // ---------- Layer 1 forward half (blocks 0..26) ----------
    const float* gm1 = l1m + n * (25 * STAGE_FLOATS);
    for (int i = t; i < FWD_STAGES * 64; i += 32)
        l2_prefetch_line(gm1 + i * 32);
    if (n == 0) {
        for (int i = t; i < 25 * 64; i += 32)
            l2_prefetch_line(fm + i * 32);
    }
    spin_until(&g_grp[n], 27u);

    if (t < 27) {
        const int bh = n / 9, bv = (n / 3) % 3, bd = n % 3;
        const int x = t / 9, y = (t / 3) % 3, z = t % 3;
        const float val = __ldcg(&g_out0[(3 * bh + x) * 81 + (3 * bv + y) * 9 + (3 * bd + z)]);
        sincosf(PI_HALF * val, &semb, &cemb);
    }
    {
        const float c0 = __shfl_sync(FULL, cemb, 0);
        const float s0 = __shfl_sync(FULL, semb, 0);
        const float* f1 = l1f + n * 64;
        float v = fmaf(f1[t], c0, f1[32 + t] * s0);
        v = chain_fwd_wide(gm1, FWD_STAGES, v, cemb, semb, t);

        spin_until(&g_half1[n], 1u);
        const float uR = __ldcg(&g_uR1[n * 32 + t]);
        const float r = warp_sum(v * uR);
        if (t == 0) {
            g_out1[n] = r;
            __threadfence();
            atomicAdd(&g_ctr1, 1u);
        }
    }
    if (n != 0) return;

    // ---------- Final layer (block 0): full backward chain (L2-warm) ----------
    spin_until(&g_ctr1, 27u);

    if (t < 27) {
        // (3,3,3) squeeze of g_out1 is the identity permutation
        const float val = __ldcg(&g_out1[t]);
        sincosf(PI_HALF * val, &semb, &cemb);
    }
    const float c26 = __shfl_sync(FULL, cemb, 26);
    const float s26 = __shfl_sync(FULL, semb, 26);
    float u = fmaf(fl[2 * t], c26, fl[2 * t + 1] * s26);
#pragma unroll 1
    for (int m = 24; m >= 0; m--) {
        const float c = __shfl_sync(FULL, cemb, m + 1);
        const float s = __shfl_sync(FULL, semb, m + 1);
        u = step_bwd(fm + m * STAGE_FLOATS, u, t, c, s);
    }
    const float c0 = __shfl_sync(FULL, cemb, 0);
    const float s0 = __shfl_sync(FULL, semb, 0);
#pragma unroll
    for (int o = 0; o < 10; o++) {
        float p = fmaf(ff[o * 32 + t], c0, ff[320 + o * 32 + t] * s0) * u;
        p = warp_sum(p);
        if (t == 0) out[o] = p;
    }
}

extern "C" void kernel_launch(void* const* d_in, const int* in_sizes, int n_in,
                              void* d_out, int out_size)
{
    const float* img      = (const float*)d_in[0];
    const float* l0_first = (const float*)d_in[1];
    const float* l0_mid   = (const float*)d_in[2];
    const float* l0_last  = (const float*)d_in[3];
    const float* l1_first = (const float*)d_in[4];
    const float* l1_mid   = (const float*)d_in[5];
    const float* l1_last  = (const float*)d_in[6];
    const float* f_first  = (const float*)d_in[7];
    const float* f_mid    = (const float*)d_in[8];
    const float* f_last   = (const float*)d_in[9];
    float* out = (float*)d_out;

    reset_kernel<<<1, 32>>>();
    fused_kernel<<<729, 32>>>(img, l0_first, l0_mid, l0_last,
                              l1_first, l1_mid, l1_last,
                              f_first, f_mid, f_last, out);
}

// round 13
// speedup vs baseline: 1.0356x; 1.0356x over previous
#include <cuda_runtime.h>
#include <cuda_bf16.h>
#include <math.h>
#include <stdint.h>

// Inter-layer scratch + sync (allocation-free rule: __device__ globals).
__device__ float g_out0[729];
__device__ float g_out1[27];
__device__ float g_uR1[27 * 32];     // layer1 backward half-results
__device__ float g_w[32];            // final backward half-result
__device__ unsigned g_grp[27];       // per-layer1-chain producer counters
__device__ unsigned g_half1[27];     // layer1 backward-half done flags
__device__ unsigned g_ctr1;          // layer1 completion counter
__device__ unsigned g_wflag;         // final backward-half done flag
__device__ unsigned g_ticket;        // tail-role work-stealing ticket

#define PI_HALF 1.57079632679489662f
#define SF 2048                       // floats per stage
#define FULL 0xffffffffu

// ---------------- helpers ----------------
__device__ __forceinline__ float warp_sum(float v) {
#pragma unroll
    for (int o = 16; o > 0; o >>= 1)
        v += __shfl_down_sync(FULL, v, o);
    return v;
}
__device__ __forceinline__ void l2_prefetch_line(const float* p) {
    asm volatile("prefetch.global.L2 [%0];" :: "l"(p));
}
__device__ __forceinline__ void spin_until(const unsigned* c, unsigned target) {
    unsigned v;
    do {
        asm volatile("ld.global.acquire.gpu.u32 %0, [%1];"
                     : "=r"(v) : "l"(c) : "memory");
        if (v >= target) return;
        __nanosleep(128);
    } while (true);
}

// R1-proven chain loop: smem bond vector, 64 coalesced LDGs per stage,
// no in-loop global barriers. vbuf holds v on entry, result on exit.
__device__ __forceinline__ void chain_lds(const float* __restrict__ mid, int nst,
                                          const float* sc1, const float* ss1,
                                          float* vbuf, int t)
{
#pragma unroll 1
    for (int m = 0; m < nst; m++) {
        const float* __restrict__ A = mid + m * SF;
        const float c = sc1[m], s = ss1[m];
        float acc = 0.0f;
#pragma unroll
        for (int d = 0; d < 32; d++)
            acc = fmaf(vbuf[d], fmaf(A[d * 64 + t], c, A[d * 64 + 32 + t] * s), acc);
        __syncwarp();
        vbuf[t] = acc;
        __syncwarp();
    }
}

// Backward step (tail only, L2-warm data, few warps): per-lane row loads.
// u_new[t] = c*(A[t][0][:]·u) + s*(A[t][1][:]·u)
__device__ __forceinline__ float step_bwd(const float* __restrict__ g, float u,
                                          int t, float c, float s) {
    const float4* __restrict__ rp = (const float4*)(g + t * 64);
    float4 q[16];
#pragma unroll
    for (int i = 0; i < 16; i++) q[i] = rp[i];
    float acc0 = 0.f, acc1 = 0.f;
#pragma unroll
    for (int i = 0; i < 8; i++) {
        const float4 a = q[i];       // A[t][0][4i..4i+3]
        const float4 b = q[8 + i];   // A[t][1][4i..4i+3]
        float ue;
        ue = __shfl_sync(FULL, u, 4 * i + 0);
        acc0 = fmaf(a.x, ue, acc0);  acc1 = fmaf(b.x, ue, acc1);
        ue = __shfl_sync(FULL, u, 4 * i + 1);
        acc0 = fmaf(a.y, ue, acc0);  acc1 = fmaf(b.y, ue, acc1);
        ue = __shfl_sync(FULL, u, 4 * i + 2);
        acc0 = fmaf(a.z, ue, acc0);  acc1 = fmaf(b.z, ue, acc1);
        ue = __shfl_sync(FULL, u, 4 * i + 3);
        acc0 = fmaf(a.w, ue, acc0);  acc1 = fmaf(b.w, ue, acc1);
    }
    return fmaf(acc0, c, acc1 * s);
}

__global__ void reset_kernel() {
    const int i = threadIdx.x;
    if (i < 27) { g_grp[i] = 0; g_half1[i] = 0; }
    if (i == 27) g_ctr1 = 0;
    if (i == 28) g_wflag = 0;
    if (i == 29) g_ticket = 0;
}

// 729 blocks x 32 threads, one wave. Every block: one layer0 chain.
// The 65 earliest finishers claim tail roles via ticket:
//   tk  0..26 : layer1 forward half of chain tk (+ combine)
//   tk 27..53 : layer1 backward half of chain tk-27
//   tk 54..63 : final output row-chain o = tk-54
//   tk 64     : final backward half (w)
__global__ void __launch_bounds__(32)
fused_kernel(const float* __restrict__ img,
             const float* __restrict__ l0f, const float* __restrict__ l0m,
             const float* __restrict__ l0l,
             const float* __restrict__ l1f, const float* __restrict__ l1m,
             const float* __restrict__ l1l,
             const float* __restrict__ ff,  const float* __restrict__ fm,
             const float* __restrict__ fl,
             float* __restrict__ out)
{
    __shared__ float sc[27], ss[27], vbuf[32];
    const int n = blockIdx.x;
    const int t = threadIdx.x;

    // ---------- Layer 0 (R1-proven path) ----------
    if (t < 27) {
        const int bh = n / 81, bv = (n / 9) % 9, bd = n % 9;
        const int x = t / 9, y = (t / 3) % 3, z = t % 3;
        const float val = img[(3 * bh + x) * 729 + (3 * bv + y) * 27 + (3 * bd + z)];
        float cv, sv;
        sincosf(PI_HALF * val, &sv, &cv);
        sc[t] = cv; ss[t] = sv;
    }
    __syncwarp();
    {
        const float* f0 = l0f + n * 64;
        vbuf[t] = fmaf(f0[t], sc[0], f0[32 + t] * ss[0]);
    }
    __syncwarp();
    const float* gm0 = l0m + (long)n * (25 * SF);
    chain_lds(gm0, 25, sc + 1, ss + 1, vbuf, t);
    {
        const float* ln = l0l + n * 64;
        const float pv = vbuf[t] * fmaf(ln[2 * t], sc[26], ln[2 * t + 1] * ss[26]);
        const float r = warp_sum(pv);
        if (t == 0) {
            g_out0[n] = r;
            __threadfence();
            const int X = n / 81, Y = (n / 9) % 9, Z = n % 9;
            atomicAdd(&g_grp[(X / 3) * 9 + (Y / 3) * 3 + (Z / 3)], 1u);
        }
    }

    // ---------- Tail role claim (finish-order work stealing) ----------
    unsigned tk = 0;
    if (t == 0) tk = atomicAdd(&g_ticket, 1u);
    tk = __shfl_sync(FULL, tk, 0);
    if (tk >= 65) return;

    if (tk < 27) {
        // ===== Layer1 forward half, chain c (+ combine) =====
        const int c = tk;
        const float* gm1 = l1m + c * (25 * SF);
        for (int i = t; i < 13 * 64; i += 32)          // L2-warm stages 0..12
            l2_prefetch_line(gm1 + i * 32);
        spin_until(&g_grp[c], 27u);

        __syncwarp();
        if (t < 27) {
            const int bh = c / 9, bv = (c / 3) % 3, bd = c % 3;
            const int x = t / 9, y = (t / 3) % 3, z = t % 3;
            const float val = __ldcg(&g_out0[(3 * bh + x) * 81 + (3 * bv + y) * 9 + (3 * bd + z)]);
            float cv, sv;
            sincosf(PI_HALF * val, &sv, &cv);
            sc[t] = cv; ss[t] = sv;
        }
        __syncwarp();
        {
            const float* f1 = l1f + c * 64;
            vbuf[t] = fmaf(f1[t], sc[0], f1[32 + t] * ss[0]);
        }
        __syncwarp();
        chain_lds(gm1, 13, sc + 1, ss + 1, vbuf, t);   // stages 0..12

        spin_until(&g_half1[c], 1u);
        const float uR = __ldcg(&g_uR1[c * 32 + t]);
        const float r = warp_sum(vbuf[t] * uR);
        if (t == 0) {
            g_out1[c] = r;
            __threadfence();
            atomicAdd(&g_ctr1, 1u);
        }
        return;
    }

    if (tk < 54) {
        // ===== Layer1 backward half, chain c =====
        const int c = tk - 27;
        const float* gm1 = l1m + c * (25 * SF);
        for (int i = t; i < 12 * 64; i += 32)          // L2-warm stages 13..24
            l2_prefetch_line(gm1 + 13 * SF + i * 32);
        spin_until(&g_grp[c], 27u);

        __syncwarp();
        if (t < 27) {
            const int bh = c / 9, bv = (c / 3) % 3, bd = c % 3;
            const int x = t / 9, y = (t / 3) % 3, z = t % 3;
            const float val = __ldcg(&g_out0[(3 * bh + x) * 81 + (3 * bv + y) * 9 + (3 * bd + z)]);
            float cv, sv;
            sincosf(PI_HALF * val, &sv, &cv);
            sc[t] = cv; ss[t] = sv;
        }
        __syncwarp();

        const float* l1 = l1l + c * 64;
        float u = fmaf(l1[2 * t], sc[26], l1[2 * t + 1] * ss[26]);
#pragma unroll 1
        for (int m = 24; m >= 13; m--)
            u = step_bwd(gm1 + m * SF, u, t, sc[m + 1], ss[m + 1]);
        g_uR1[c * 32 + t] = u;
        __threadfence();
        if (t == 0) atomicAdd(&g_half1[c], 1u);
        return;
    }

    if (tk < 64) {
        // ===== Final forward row-chain for output o =====
        const int o = tk - 54;
        for (int i = t; i < 13 * 64; i += 32)          // L2-warm fm stages 0..12
            l2_prefetch_line(fm + i * 32);
        spin_until(&g_ctr1, 27u);

        __syncwarp();
        if (t < 27) {
            // (3,3,3) squeeze of g_out1 is the identity permutation
            float cv, sv;
            sincosf(PI_HALF * __ldcg(&g_out1[t]), &sv, &cv);
            sc[t] = cv; ss[t] = sv;
        }
        __syncwarp();
        vbuf[t] = fmaf(ff[o * 32 + t], sc[0], ff[320 + o * 32 + t] * ss[0]);
        __syncwarp();
        chain_lds(fm, 13, sc + 1, ss + 1, vbuf, t);    // stages 0..12

        spin_until(&g_wflag, 1u);
        const float w = __ldcg(&g_w[t]);
        const float p = warp_sum(vbuf[t] * w);
        if (t == 0) out[o] = p;
        return;
    }

    // ===== tk == 64: final backward half w = M13..M24 * last_emb =====
    for (int i = t; i < 12 * 64; i += 32)              // L2-warm fm stages 13..24
        l2_prefetch_line(fm + 13 * SF + i * 32);
    spin_until(&g_ctr1, 27u);

    __syncwarp();
    if (t < 27) {
        float cv, sv;
        sincosf(PI_HALF * __ldcg(&g_out1[t]), &sv, &cv);
        sc[t] = cv; ss[t] = sv;
    }
    __syncwarp();

    float u = fmaf(fl[2 * t], sc[26], fl[2 * t + 1] * ss[26]);
#pragma unroll 1
    for (int m = 24; m >= 13; m--)
        u = step_bwd(fm + m * SF, u, t, sc[m + 1], ss[m + 1]);
    g_w[t] = u;
    __threadfence();
    if (t == 0) atomicAdd(&g_wflag, 1u);
}

extern "C" void kernel_launch(void* const* d_in, const int* in_sizes, int n_in,
                              void* d_out, int out_size)
{
    const float* img      = (const float*)d_in[0];
    const float* l0_first = (const float*)d_in[1];
    const float* l0_mid   = (const float*)d_in[2];
    const float* l0_last  = (const float*)d_in[3];
    const float* l1_first = (const float*)d_in[4];
    const float* l1_mid   = (const float*)d_in[5];
    const float* l1_last  = (const float*)d_in[6];
    const float* f_first  = (const float*)d_in[7];
    const float* f_mid    = (const float*)d_in[8];
    const float* f_last   = (const float*)d_in[9];
    float* out = (float*)d_out;

    reset_kernel<<<1, 32>>>();
    fused_kernel<<<729, 32>>>(img, l0_first, l0_mid, l0_last,
                              l1_first, l1_mid, l1_last,
                              f_first, f_mid, f_last, out);
}

// round 14
// speedup vs baseline: 1.4056x; 1.3573x over previous
#include <cuda_runtime.h>
#include <cuda_bf16.h>
#include <math.h>
#include <stdint.h>

// Inter-layer scratch + sync (allocation-free rule: __device__ globals).
__device__ float g_out0[729];
__device__ float g_out1[27];
__device__ float g_w[32];            // final backward half-result
__device__ unsigned g_grp[27];       // per-layer1-chain producer counters (27 each)
__device__ unsigned g_ctr1;          // layer1 completion counter
__device__ unsigned g_wflag;         // final backward-half done flag

#define PI_HALF 1.57079632679489662f
#define DEPTH 5
#define STAGE_FLOATS 2048
#define STAGE_BYTES 8192
#define SMEM_DYN (DEPTH * STAGE_BYTES)   // 40 KB -> 5 CTAs/SM, all 729 resident
#define FULL 0xffffffffu

// ---------------- helpers (verbatim from the 49.6us kernel) ----------------
__device__ __forceinline__ uint32_t smem_u32(const void* p) {
    return (uint32_t)__cvta_generic_to_shared(p);
}
__device__ __forceinline__ void cpa16(uint32_t d, const float* s) {
    asm volatile("cp.async.cg.shared.global [%0], [%1], 16;" :: "r"(d), "l"(s) : "memory");
}
__device__ __forceinline__ void cp_commit() {
    asm volatile("cp.async.commit_group;" ::: "memory");
}
__device__ __forceinline__ void cp_wait4() {
    asm volatile("cp.async.wait_group 4;" ::: "memory");
}
__device__ __forceinline__ void l2_prefetch_line(const float* p) {
    asm volatile("prefetch.global.L2 [%0];" :: "l"(p));
}
__device__ __forceinline__ float warp_sum(float v) {
#pragma unroll
    for (int o = 16; o > 0; o >>= 1)
        v += __shfl_down_sync(FULL, v, o);
    return v;
}
__device__ __forceinline__ void spin_until(const unsigned* c, unsigned target) {
    unsigned v;
    do {
        asm volatile("ld.global.acquire.gpu.u32 %0, [%1];"
                     : "=r"(v) : "l"(c) : "memory");
        if (v >= target) return;
        __nanosleep(128);
    } while (true);
}

// Warp-wide issue of one 8 KB stage into ring slot (stage % DEPTH).
__device__ __forceinline__ void issue_stage(uint32_t sbase, const float* g,
                                            int stage, int t) {
    const int slot = stage % DEPTH;
    const float* src = g + stage * STAGE_FLOATS + t * 4;
    const uint32_t dst = sbase + slot * STAGE_BYTES + t * 16;
#pragma unroll
    for (int i = 0; i < 16; i++)
        cpa16(dst + i * 512, src + i * 128);
    cp_commit();
}

// Forward scalar MPS chain (one warp), cp.async DEPTH-5 ring (verbatim R4).
__device__ __forceinline__ float chain_fwd(
    const float* __restrict__ gmid, const float* __restrict__ first,
    const float* __restrict__ last, const float* sc, const float* ss,
    float* vbuf, const float* stg, uint32_t sbase, int t)
{
    vbuf[t] = fmaf(first[t], sc[0], first[32 + t] * ss[0]);
    __syncwarp();

#pragma unroll 1
    for (int m = 0; m < 25; m++) {
        cp_wait4();
        __syncwarp();                         // cross-lane visibility of stage m
        const float* __restrict__ A = stg + (m % DEPTH) * STAGE_FLOATS;
        const float c = sc[m + 1], sn = ss[m + 1];
        float acc = 0.0f;
#pragma unroll
        for (int d = 0; d < 32; d++)
            acc = fmaf(vbuf[d], fmaf(A[d * 64 + t], c, A[d * 64 + 32 + t] * sn), acc);
        __syncwarp();                         // all lanes done reading slot + vbuf
        vbuf[t] = acc;
        if (m + DEPTH < 25) issue_stage(sbase, gmid, m + DEPTH, t);
        else                cp_commit();      // empty group keeps wait math exact
        __syncwarp();
    }
    const float pv = vbuf[t] * fmaf(last[2 * t], sc[26], last[2 * t + 1] * ss[26]);
    return warp_sum(pv);
}

// Plain-LDG chain over L2-warm data (final-layer rows; perf non-critical).
__device__ __forceinline__ void chain_lds(const float* __restrict__ mid, int nst,
                                          const float* sc1, const float* ss1,
                                          float* vbuf, int t)
{
#pragma unroll 1
    for (int m = 0; m < nst; m++) {
        const float* __restrict__ A = mid + m * STAGE_FLOATS;
        const float c = sc1[m], s = ss1[m];
        float acc = 0.0f;
#pragma unroll
        for (int d = 0; d < 32; d++)
            acc = fmaf(vbuf[d], fmaf(A[d * 64 + t], c, A[d * 64 + 32 + t] * s), acc);
        __syncwarp();
        vbuf[t] = acc;
        __syncwarp();
    }
}

// Backward step via per-lane row loads (L2-warm, one warp; wavefronts harmless).
__device__ __forceinline__ float step_bwd(const float* __restrict__ g, float u,
                                          int t, float c, float s) {
    const float4* __restrict__ rp = (const float4*)(g + t * 64);
    float4 q[16];
#pragma unroll
    for (int i = 0; i < 16; i++) q[i] = rp[i];
    float acc0 = 0.f, acc1 = 0.f;
#pragma unroll
    for (int i = 0; i < 8; i++) {
        const float4 a = q[i];       // A[t][0][4i..4i+3]
        const float4 b = q[8 + i];   // A[t][1][4i..4i+3]
        float ue;
        ue = __shfl_sync(FULL, u, 4 * i + 0);
        acc0 = fmaf(a.x, ue, acc0);  acc1 = fmaf(b.x, ue, acc1);
        ue = __shfl_sync(FULL, u, 4 * i + 1);
        acc0 = fmaf(a.y, ue, acc0);  acc1 = fmaf(b.y, ue, acc1);
        ue = __shfl_sync(FULL, u, 4 * i + 2);
        acc0 = fmaf(a.z, ue, acc0);  acc1 = fmaf(b.z, ue, acc1);
        ue = __shfl_sync(FULL, u, 4 * i + 3);
        acc0 = fmaf(a.w, ue, acc0);  acc1 = fmaf(b.w, ue, acc1);
    }
    return fmaf(acc0, c, acc1 * s);
}

__global__ void reset_kernel() {
    if (threadIdx.x < 27) g_grp[threadIdx.x] = 0;
    if (threadIdx.x == 27) g_ctr1 = 0;
    if (threadIdx.x == 28) g_wflag = 0;
}

// Persistent fused kernel: 729 blocks x 32 threads, one wave.
//   all blocks : layer0 chain n.
//   n 0..26    : layer1 chain n (R4 ring, verbatim).
//   n 27..36   : final output row o = n-27 (forward 13 stages from L2).
//   n 37       : final backward half (stages 24..13 from L2).
__global__ void __launch_bounds__(32)
fused_kernel(const float* __restrict__ img,
             const float* __restrict__ l0f, const float* __restrict__ l0m,
             const float* __restrict__ l0l,
             const float* __restrict__ l1f, const float* __restrict__ l1m,
             const float* __restrict__ l1l,
             const float* __restrict__ ff,  const float* __restrict__ fm,
             const float* __restrict__ fl,
             float* __restrict__ out)
{
    extern __shared__ float stg[];                  // DEPTH x 2048 floats
    __shared__ float sc[27], ss[27], vbuf[32];

    const int n = blockIdx.x;
    const int t = threadIdx.x;
    const uint32_t sbase = smem_u32(stg);

    // ---------- Layer 0 (verbatim R4) ----------
    const float* gm0 = l0m + (long)n * (25 * STAGE_FLOATS);
#pragma unroll
    for (int s = 0; s < DEPTH; s++) issue_stage(sbase, gm0, s, t);

    if (t < 27) {
        const int bh = n / 81, bv = (n / 9) % 9, bd = n % 9;
        const int x = t / 9, y = (t / 3) % 3, z = t % 3;
        const float val = img[(3 * bh + x) * 729 + (3 * bv + y) * 27 + (3 * bd + z)];
        float cv, sv;
        sincosf(PI_HALF * val, &sv, &cv);
        sc[t] = cv; ss[t] = sv;
    }
    __syncwarp();

    float r = chain_fwd(gm0, l0f + n * 64, l0l + n * 64, sc, ss, vbuf, stg, sbase, t);
    if (t == 0) {
        g_out0[n] = r;
        __threadfence();
        const int X = n / 81, Y = (n / 9) % 9, Z = n % 9;
        atomicAdd(&g_grp[(X / 3) * 9 + (Y / 3) * 3 + (Z / 3)], 1u);
    }
    if (n >= 38) return;

    if (n < 27) {
        // ---------- Layer 1 (blocks 0..26, verbatim R4 ring) ----------
        const float* gm1 = l1m + n * (25 * STAGE_FLOATS);
#pragma unroll
        for (int s = 0; s < DEPTH; s++) issue_stage(sbase, gm1, s, t);
        {
            const float* pf = gm1 + DEPTH * STAGE_FLOATS;   // remaining 20 stages
            for (int i = t; i < 20 * STAGE_FLOATS / 32; i += 32)
                l2_prefetch_line(pf + i * 32);
        }
        spin_until(&g_grp[n], 27u);

        __syncwarp();
        if (t < 27) {
            const int bh = n / 9, bv = (n / 3) % 3, bd = n % 3;
            const int x = t / 9, y = (t / 3) % 3, z = t % 3;
            const float val = __ldcg(&g_out0[(3 * bh + x) * 81 + (3 * bv + y) * 9 + (3 * bd + z)]);
            float cv, sv;
            sincosf(PI_HALF * val, &sv, &cv);
            sc[t] = cv; ss[t] = sv;
        }
        __syncwarp();

        r = chain_fwd(gm1, l1f + n * 64, l1l + n * 64, sc, ss, vbuf, stg, sbase, t);
        if (t == 0) {
            g_out1[n] = r;
            __threadfence();
            atomicAdd(&g_ctr1, 1u);
        }
        return;
    }

    // ---------- Final layer, parallel split (blocks 27..37) ----------
    if (n < 37) {
        // Forward 13-stage chain for output row o = n-27.
        const int o = n - 27;
        for (int i = t; i < 13 * 64; i += 32)              // L2-warm fm stages 0..12
            l2_prefetch_line(fm + i * 32);
        spin_until(&g_ctr1, 27u);

        __syncwarp();
        if (t < 27) {
            // (3,3,3) squeeze of g_out1 is the identity permutation
            float cv, sv;
            sincosf(PI_HALF * __ldcg(&g_out1[t]), &sv, &cv);
            sc[t] = cv; ss[t] = sv;
        }
        __syncwarp();
        vbuf[t] = fmaf(ff[o * 32 + t], sc[0], ff[320 + o * 32 + t] * ss[0]);
        __syncwarp();
        chain_lds(fm, 13, sc + 1, ss + 1, vbuf, t);        // stages 0..12

        spin_until(&g_wflag, 1u);
        const float w = __ldcg(&g_w[t]);
        const float p = warp_sum(vbuf[t] * w);
        if (t == 0) out[o] = p;
        return;
    }

    // Block 37: backward half w = M13..M24 * last_emb.
    for (int i = t; i < 12 * 64; i += 32)                  // L2-warm fm stages 13..24
        l2_prefetch_line(fm + 13 * STAGE_FLOATS + i * 32);
    spin_until(&g_ctr1, 27u);

    __syncwarp();
    if (t < 27) {
        float cv, sv;
        sincosf(PI_HALF * __ldcg(&g_out1[t]), &sv, &cv);
        sc[t] = cv; ss[t] = sv;
    }
    __syncwarp();

    float u = fmaf(fl[2 * t], sc[26], fl[2 * t + 1] * ss[26]);
#pragma unroll 1
    for (int m = 24; m >= 13; m--)
        u = step_bwd(fm + m * STAGE_FLOATS, u, t, sc[m + 1], ss[m + 1]);
    g_w[t] = u;
    __threadfence();
    if (t == 0) atomicAdd(&g_wflag, 1u);
}

extern "C" void kernel_launch(void* const* d_in, const int* in_sizes, int n_in,
                              void* d_out, int out_size)
{
    const float* img      = (const float*)d_in[0];
    const float* l0_first = (const float*)d_in[1];
    const float* l0_mid   = (const float*)d_in[2];
    const float* l0_last  = (const float*)d_in[3];
    const float* l1_first = (const float*)d_in[4];
    const float* l1_mid   = (const float*)d_in[5];
    const float* l1_last  = (const float*)d_in[6];
    const float* f_first  = (const float*)d_in[7];
    const float* f_mid    = (const float*)d_in[8];
    const float* f_last   = (const float*)d_in[9];
    float* out = (float*)d_out;

    reset_kernel<<<1, 32>>>();
    fused_kernel<<<729, 32, SMEM_DYN>>>(img, l0_first, l0_mid, l0_last,
                                        l1_first, l1_mid, l1_last,
                                        f_first, f_mid, f_last, out);
}